// round 6
// baseline (speedup 1.0000x reference)
#include <cuda_runtime.h>
#include <math_constants.h>

// Problem constants (fixed by the reference)
#define BB 2
#define TT 512
#define EE 1024
#define SS 2048
#define AA 30

#define BUCKET   16                   // start values per bucket
#define NBUCK    (TT / BUCKET)        // 32 buckets
#define ROWS_MAX (BUCKET + AA - 1)    // 45 rows touched by a bucket
#define EQ       128                  // columns handled per block (E/8)
#define NH       (EE / EQ)            // 8 E-slices
#define C4Q      (EQ / 4)             // 32 float4 per row
#define LISTN    1024                 // parity split -> at most SS/2 spans/half

// smem: x tile [ROWS_MAX][C4Q] float4 (23040 B) + span list [LISTN] int (4 KB)
#define TILE_BYTES (ROWS_MAX * C4Q * 16)
#define SMEM_BYTES (TILE_BYTES + LISTN * 4)

__device__ float g_scores[BB * TT];
__device__ float g_probs[BB * SS * 32];

// ---------------------------------------------------------------------------
// Kernel 1: scores[b,t] = relu(dot(x[b,t,:], W) + bias).
// One BLOCK per row (1024 blocks): 256 threads x float4 = 1024 floats.
// ---------------------------------------------------------------------------
__global__ __launch_bounds__(256)
void score_kernel(const float* __restrict__ x,
                  const float* __restrict__ W,
                  const float* __restrict__ bias) {
    __shared__ float red[8];
    const int row  = blockIdx.x;
    const int tid  = threadIdx.x;
    const int lane = tid & 31;
    const int wrp  = tid >> 5;

    const float4 xv = reinterpret_cast<const float4*>(x)[(size_t)row * 256 + tid];
    const float4 wv = reinterpret_cast<const float4*>(W)[tid];
    float acc = xv.x * wv.x + xv.y * wv.y + xv.z * wv.z + xv.w * wv.w;

#pragma unroll
    for (int off = 16; off; off >>= 1)
        acc += __shfl_xor_sync(0xffffffffu, acc, off);
    if (lane == 0) red[wrp] = acc;
    __syncthreads();

    if (tid == 0) {
        float s = red[0];
#pragma unroll
        for (int i = 1; i < 8; ++i) s += red[i];
        g_scores[row] = fmaxf(s + bias[0], 0.0f);
    }
}

// ---------------------------------------------------------------------------
// Kernel 2: softmax probs per (b,s) -> g_probs[b][s][lane] (0 for lane >= w).
// One warp per (b,s). Computed exactly once chip-wide.
// ---------------------------------------------------------------------------
__global__ __launch_bounds__(256)
void prob_kernel(const int* __restrict__ start,
                 const int* __restrict__ end) {
    const int wid  = blockIdx.x * 8 + (threadIdx.x >> 5);   // 0 .. B*S-1
    const int lane = threadIdx.x & 31;
    const int s = wid & (SS - 1);
    const int b = wid >> 11;

    const int t0 = start[s];
    const int w  = end[s] - t0 + 1;                          // 1..30

    float sc = (lane < w) ? g_scores[b * TT + t0 + lane] : -CUDART_INF_F;
    float m = sc;
#pragma unroll
    for (int off = 16; off; off >>= 1)
        m = fmaxf(m, __shfl_xor_sync(0xffffffffu, m, off));
    float e = (lane < w) ? __expf(sc - m) : 0.0f;
    float sum = e;
#pragma unroll
    for (int off = 16; off; off >>= 1)
        sum += __shfl_xor_sync(0xffffffffu, sum, off);

    g_probs[((size_t)b * SS + s) * 32 + lane] = e / sum;
}

// ---------------------------------------------------------------------------
// Kernel 3: bucketed span pooling, warp-per-span from a small shared tile.
// Block = (bucket kb, E-slice h, batch b, span-parity half).
// 32*8*2*2 = 1024 blocks, 27.1 KB smem -> 8 blocks/SM, ~full occupancy.
// ---------------------------------------------------------------------------
extern __shared__ char smem_raw[];

__global__ __launch_bounds__(256)
void span_tile_kernel(const float* __restrict__ x,
                      const int* __restrict__ start,
                      const int* __restrict__ end,
                      float* __restrict__ out) {
    float4* xs   = reinterpret_cast<float4*>(smem_raw);              // [ROWS_MAX][C4Q]
    int*    list = reinterpret_cast<int*>(smem_raw + TILE_BYTES);    // [LISTN]
    __shared__ int cnt;

    const int tid  = threadIdx.x;
    const int lane = tid & 31;
    const int wrp  = tid >> 5;
    const int kb   = blockIdx.x;          // bucket
    const int h    = blockIdx.y;          // E-slice
    const int bz   = blockIdx.z;          // batch * 2 + half
    const int b    = bz >> 1;
    const int half = bz & 1;
    const int base = kb * BUCKET;

    if (tid == 0) cnt = 0;
    __syncthreads();

    // ---- collect this bucket-half's spans into smem list ----
#pragma unroll
    for (int i = 0; i < SS / 256; ++i) {
        const int s = tid + i * 256;
        const unsigned d = (unsigned)(start[s] - base);
        if (d < BUCKET && (s & 1) == half) {
            const int pos = atomicAdd(&cnt, 1);
            list[pos] = s;
        }
    }

    // ---- load x tile (rows base..base+nr-1, this E-slice) into smem ----
    const int nr = min(ROWS_MAX, TT - base);
    const float4* __restrict__ x4 =
        reinterpret_cast<const float4*>(x + ((size_t)b * TT + base) * EE + h * EQ);
    for (int i = tid; i < nr * C4Q; i += 256) {
        const int r = i >> 5;             // / C4Q (=32)
        const int c = i & (C4Q - 1);
        xs[r * C4Q + c] = x4[(size_t)r * (EE / 4) + c];
    }
    __syncthreads();

    const int n = cnt;

    // ---- each warp serves spans independently ----
    for (int idx = wrp; idx < n; idx += 8) {
        const int s  = list[idx];
        const int t0 = start[s];
        const int w  = end[s] - t0 + 1;   // 1..30
        const int r0 = t0 - base;

        // lane j holds p_j (0 for j >= w), precomputed by prob_kernel
        const float p = g_probs[((size_t)b * SS + s) * 32 + lane];

        float4 acc = make_float4(0.0f, 0.0f, 0.0f, 0.0f);
        const float4* __restrict__ row = xs + r0 * C4Q + lane;

        int j = 0;
#pragma unroll 1
        for (; j + 4 <= w; j += 4) {
            const float p0 = __shfl_sync(0xffffffffu, p, j);
            const float p1 = __shfl_sync(0xffffffffu, p, j + 1);
            const float p2 = __shfl_sync(0xffffffffu, p, j + 2);
            const float p3 = __shfl_sync(0xffffffffu, p, j + 3);
            const float4 v0 = row[(j)     * C4Q];
            const float4 v1 = row[(j + 1) * C4Q];
            const float4 v2 = row[(j + 2) * C4Q];
            const float4 v3 = row[(j + 3) * C4Q];
            acc.x += p0 * v0.x + p1 * v1.x + p2 * v2.x + p3 * v3.x;
            acc.y += p0 * v0.y + p1 * v1.y + p2 * v2.y + p3 * v3.y;
            acc.z += p0 * v0.z + p1 * v1.z + p2 * v2.z + p3 * v3.z;
            acc.w += p0 * v0.w + p1 * v1.w + p2 * v2.w + p3 * v3.w;
        }
        for (; j < w; ++j) {
            const float pj = __shfl_sync(0xffffffffu, p, j);
            const float4 v = row[j * C4Q];
            acc.x += pj * v.x;
            acc.y += pj * v.y;
            acc.z += pj * v.z;
            acc.w += pj * v.w;
        }

        reinterpret_cast<float4*>(out + ((size_t)b * SS + s) * EE + h * EQ)[lane] = acc;
    }
}

// ---------------------------------------------------------------------------
// Launch
// Inputs (metadata order): x (B,T,E) f32, W (E,1) f32, b (1,) f32,
//                          start (S,) i32, end (S,) i32
// Output: (B, S, E) f32
// ---------------------------------------------------------------------------
extern "C" void kernel_launch(void* const* d_in, const int* in_sizes, int n_in,
                              void* d_out, int out_size) {
    const float* x     = (const float*)d_in[0];
    const float* W     = (const float*)d_in[1];
    const float* bias  = (const float*)d_in[2];
    const int*   start = (const int*)d_in[3];
    const int*   end   = (const int*)d_in[4];
    float*       out   = (float*)d_out;

    // Kernel 1: scores, one block per row
    score_kernel<<<BB * TT, 256>>>(x, W, bias);

    // Kernel 2: softmax probs, one warp per (b,s)
    prob_kernel<<<(BB * SS) / 8, 256>>>(start, end);

    // Kernel 3: bucketed pooling, warp-per-span, parity-split for occupancy
    dim3 grid(NBUCK, NH, BB * 2);
    span_tile_kernel<<<grid, 256, SMEM_BYTES>>>(x, start, end, out);
}